// round 10
// baseline (speedup 1.0000x reference)
#include <cuda_runtime.h>
#include <cuda_bf16.h>
#include <math.h>

// ---------------------------------------------------------------------------
// mean over all (i,j) of: same(i,j) ? max(1-cos,0) : cos, with cos = pairwise
// cosine of row-normalized inputs.
//
// Algebraic collapse (clamp provably inactive; rel_err==0.0 confirmed):
//   sum = S1.S2 + sum_c [ cnt1_c*cnt2_c - 2 * T1_c . T2_c ]
// T_c = class-sum of normalized rows.  O(N*D).
//
// R9: R8's zero-atomic structure was right; its reduce kernel was the R5
// pathology (256 strided loads @ MLP 4 -> 36us). Fix:
//   K2: 128 blocks x 64 rows -> 4MB partials (denser slices)
//   K3: 512 threads/block, 64 loads/thread @ unroll 16 (MLP 16)
// ---------------------------------------------------------------------------

#define NCLASS   16
#define NCEFF    32           // 16 classes x 2 tensors
#define DIM      256
#define DIMQ     (DIM / 4)    // 64 dim-quads
#define ROWS_PB  64
#define MAXBLK   128          // (4096+4096)/64
#define NTHREADS 256
#define NT3      512
#define ROWS_PW  8            // rows per warp in K2 norm pass

struct __align__(16) Entry {
    const float* ptr;
    float        inv;
    int          cls;
};

__device__ float4       g_part[MAXBLK][NCEFF][DIMQ];  // 4 MB, dense overwrite
__device__ int          g_cntp[MAXBLK][NCEFF];        // dense overwrite
__device__ float        g_T[NCEFF * DIM];             // K3 overwrites
__device__ int          g_cnt[NCEFF];
__device__ unsigned int g_done;

// ======================= K2: per-block partial tiles ========================
__global__ void __launch_bounds__(NTHREADS)
ci_partial_kernel(const float* __restrict__ x1,
                  const int* __restrict__ lab1, int n1,
                  const float* __restrict__ x2,
                  const int* __restrict__ lab2, int n2) {
    __shared__ Entry         sSorted[ROWS_PB];
    __shared__ const float*  sPtr[ROWS_PB];
    __shared__ int           sCls[ROWS_PB];
    __shared__ int           sPos[ROWS_PB];
    __shared__ int           sCnt[NCEFF];
    __shared__ int           sOff[NCEFF];

    const int tid  = threadIdx.x;
    const int lane = tid & 31;
    const int wid  = tid >> 5;
    const int bid  = blockIdx.x;

    if (tid < NCEFF) sCnt[tid] = 0;
    __syncthreads();

    const int ntot  = n1 + n2;
    const int base  = bid * ROWS_PB;
    const int chunk = min(ROWS_PB, ntot - base);

    // ---- prologue: labels, pointers, counts, ranks ------------------------
    if (tid < chunk) {
        int row = base + tid;
        const float* xp;
        int c;
        if (row < n1) { xp = x1 + (size_t)row * DIM;        c = lab1[row] & (NCLASS - 1); }
        else          { xp = x2 + (size_t)(row - n1) * DIM; c = (lab2[row - n1] & (NCLASS - 1)) + NCLASS; }
        sPtr[tid] = xp;
        sCls[tid] = c;
        sPos[tid] = atomicAdd(&sCnt[c], 1);
    }
    __syncthreads();

    // ---- warp 0: exclusive prefix scan of counts -> bucket offsets --------
    if (wid == 0) {
        int v = sCnt[lane];
        int s = v;
        #pragma unroll
        for (int o = 1; o < 32; o <<= 1) {
            int u = __shfl_up_sync(0xFFFFFFFFu, s, o);
            if (lane >= o) s += u;
        }
        sOff[lane] = s - v;   // exclusive
    }
    __syncthreads();

    // ---- norm pass: warp handles 8 rows, ALL 16 LDG.128 front-batched -----
    {
        const int i0 = wid * ROWS_PW;
        const float4* ps[ROWS_PW];
        #pragma unroll
        for (int j = 0; j < ROWS_PW; j++)
            ps[j] = reinterpret_cast<const float4*>(
                (i0 + j < chunk) ? sPtr[i0 + j] : x1);

        float4 A[ROWS_PW], B[ROWS_PW];
        #pragma unroll
        for (int j = 0; j < ROWS_PW; j++) {
            A[j] = ps[j][lane * 2];
            B[j] = ps[j][lane * 2 + 1];
        }
        float ss[ROWS_PW];
        #pragma unroll
        for (int j = 0; j < ROWS_PW; j++)
            ss[j] = A[j].x * A[j].x + A[j].y * A[j].y + A[j].z * A[j].z + A[j].w * A[j].w
                  + B[j].x * B[j].x + B[j].y * B[j].y + B[j].z * B[j].z + B[j].w * B[j].w;
        #pragma unroll
        for (int o = 16; o > 0; o >>= 1) {
            #pragma unroll
            for (int j = 0; j < ROWS_PW; j++)
                ss[j] += __shfl_xor_sync(0xFFFFFFFFu, ss[j], o);
        }
        if (lane == 0) {
            #pragma unroll
            for (int j = 0; j < ROWS_PW; j++) {
                int i = i0 + j;
                if (i < chunk) {
                    int c   = sCls[i];
                    int idx = sOff[c] + sPos[i];
                    sSorted[idx].ptr = (const float*)ps[j];
                    sSorted[idx].inv = 1.0f / fmaxf(sqrtf(ss[j]), 1e-8f);
                    sSorted[idx].cls = c;
                }
            }
        }
    }
    __syncthreads();

    // ---- phase B: scan sorted runs; dense STG partial tile ------------------
    // group gq (64 threads) owns classes [8gq, 8gq+8); thread owns quad q.
    {
        const int gq = tid >> 6;          // 0..3
        const int q  = tid & (DIMQ - 1);  // 0..63
        #pragma unroll
        for (int ci = 0; ci < 8; ci++) {
            int c = gq * 8 + ci;
            int s = sOff[c];
            int e = s + sCnt[c];
            float4 acc = make_float4(0.f, 0.f, 0.f, 0.f);
            for (int k = s; k < e; k++) {
                Entry en = sSorted[k];                                  // bcast LDS.128
                float4 v = reinterpret_cast<const float4*>(en.ptr)[q];  // L1 hit
                acc.x += v.x * en.inv;
                acc.y += v.y * en.inv;
                acc.z += v.z * en.inv;
                acc.w += v.w * en.inv;
            }
            g_part[bid][c][q] = acc;   // plain STG.128
        }
    }
    if (tid < NCEFF) g_cntp[bid][tid] = sCnt[tid];
}

// ======================= K3: reduce partials + finalize =====================
__global__ void __launch_bounds__(NT3)
ci_reduce_kernel(float* __restrict__ out, int nblk, int n1, int n2) {
    __shared__ float        sPart[2][DIM];
    __shared__ int          sCntArr[MAXBLK];
    __shared__ unsigned int sIsLast;
    __shared__ double       sRed[DIM / 32];

    const int tid  = threadIdx.x;
    const int lane = tid & 31;
    const int c    = blockIdx.x;     // one block per effective class
    const int d    = tid & (DIM - 1);
    const int half = tid >> 8;       // 0 or 1

    // ---- sum this class's partials: 64 slices per half, MLP 16 -------------
    {
        const float* pc = (const float*)&g_part[0][c][0];
        const int sstride = NCEFF * DIM;            // floats between slices
        const int b0   = half * (nblk >> 1);
        const int bcnt = nblk >> 1;                 // 64
        float a[4] = {0.f, 0.f, 0.f, 0.f};
        #pragma unroll 4
        for (int b = 0; b < bcnt; b += 4) {
            a[0] += pc[(size_t)(b0 + b + 0) * sstride + d];
            a[1] += pc[(size_t)(b0 + b + 1) * sstride + d];
            a[2] += pc[(size_t)(b0 + b + 2) * sstride + d];
            a[3] += pc[(size_t)(b0 + b + 3) * sstride + d];
        }
        sPart[half][d] = (a[0] + a[1]) + (a[2] + a[3]);
    }

    // ---- counts: threads 0..nblk-1 stage, thread 0 sums ---------------------
    if (tid < nblk) sCntArr[tid] = g_cntp[tid][c];
    __syncthreads();

    if (tid < DIM)
        g_T[c * DIM + d] = sPart[0][d] + sPart[1][d];
    if (tid == 0) {
        int t = 0;
        for (int b = 0; b < nblk; b++) t += sCntArr[b];
        g_cnt[c] = t;
    }

    // ---- tiny election over NCEFF blocks ------------------------------------
    __threadfence();
    __syncthreads();
    if (tid == 0)
        sIsLast = (atomicAdd(&g_done, 1u) == (unsigned)(NCEFF - 1));
    __syncthreads();
    if (!sIsLast) return;

    // ---- finalize (first 256 threads) ----------------------------------------
    double part = 0.0;
    if (tid < DIM) {
        double s1 = 0.0, s2 = 0.0, t = 0.0;
        #pragma unroll
        for (int cc = 0; cc < NCLASS; cc++) {
            double av = (double)g_T[cc * DIM + d];
            double bv = (double)g_T[(cc + NCLASS) * DIM + d];
            s1 += av;
            s2 += bv;
            t  += av * bv;
        }
        part = s1 * s2 - 2.0 * t;
    }
    #pragma unroll
    for (int o = 16; o > 0; o >>= 1)
        part += __shfl_xor_sync(0xFFFFFFFFu, part, o);
    if (tid < DIM && lane == 0) sRed[tid >> 5] = part;
    __syncthreads();
    if (tid == 0) {
        double tot = 0.0;
        #pragma unroll
        for (int w = 0; w < DIM / 32; w++) tot += sRed[w];
        double cc = 0.0;
        #pragma unroll
        for (int k = 0; k < NCLASS; k++)
            cc += (double)g_cnt[k] * (double)g_cnt[k + NCLASS];
        out[0] = (float)((tot + cc) / ((double)n1 * (double)n2));
        g_done = 0u;   // only residual state
    }
}

extern "C" void kernel_launch(void* const* d_in, const int* in_sizes, int n_in,
                              void* d_out, int out_size) {
    const float* mmd1 = (const float*)d_in[0];
    const float* mmd2 = (const float*)d_in[1];
    const int*   lab1 = (const int*)d_in[2];
    const int*   lab2 = (const int*)d_in[3];

    int n1 = in_sizes[0] / DIM;
    int n2 = in_sizes[1] / DIM;
    int ntot = n1 + n2;
    int nblk = (ntot + ROWS_PB - 1) / ROWS_PB;
    if (nblk > MAXBLK) nblk = MAXBLK;   // fixed shapes: 128 exactly

    ci_partial_kernel<<<nblk, NTHREADS>>>(mmd1, lab1, n1, mmd2, lab2, n2);
    ci_reduce_kernel<<<NCEFF, NT3>>>((float*)d_out, nblk, n1, n2);
}

// round 11
// speedup vs baseline: 1.3686x; 1.3686x over previous
#include <cuda_runtime.h>
#include <cuda_bf16.h>
#include <math.h>

// ---------------------------------------------------------------------------
// mean over all (i,j) of: same(i,j) ? max(1-cos,0) : cos, with cos = pairwise
// cosine of row-normalized inputs.
//
// Algebraic collapse (clamp provably inactive; rel_err==0.0 confirmed):
//   sum = S1.S2 + sum_c [ cnt1_c*cnt2_c - 2 * T1_c . T2_c ]
// T_c = class-sum of normalized rows.  O(N*D).
//
// R10: R9 split the cost cleanly: K2 (8MB input pass) = 2.7us; K3 (4MB
// partial reduce on 32 blocks @ MLP~1.7) = 28.8us. K3 is rebuilt with
// 128 blocks x 8 independent float4 loads/thread + tiny v4-RED second
// level (8K REDs total). K2 unchanged.
// ---------------------------------------------------------------------------

#define NCLASS   16
#define NCEFF    32           // 16 classes x 2 tensors
#define DIM      256
#define DIMQ     (DIM / 4)    // 64 dim-quads
#define ROWS_PB  64
#define MAXBLK   128          // (4096+4096)/64
#define NTHREADS 256
#define ROWS_PW  8            // rows per warp in K2 norm pass
#define K3BLKS   (NCEFF * 4)  // 128

struct __align__(16) Entry {
    const float* ptr;
    float        inv;
    int          cls;
};

__device__ float4       g_part[MAXBLK][NCEFF][DIMQ];  // 4 MB, dense overwrite
__device__ int          g_cntp[MAXBLK][NCEFF];        // dense overwrite
__device__ float4       g_T4[NCEFF * DIMQ];           // RED-accumulated; last K3 block zeroes
__device__ int          g_cnt[NCEFF];                 // STG overwrite
__device__ unsigned int g_done;

__device__ __forceinline__ void red_v4(float4* p, float4 v) {
    asm volatile("red.global.add.v4.f32 [%0], {%1, %2, %3, %4};"
                 :: "l"(p), "f"(v.x), "f"(v.y), "f"(v.z), "f"(v.w)
                 : "memory");
}

// ======================= K2: per-block partial tiles ========================
__global__ void __launch_bounds__(NTHREADS)
ci_partial_kernel(const float* __restrict__ x1,
                  const int* __restrict__ lab1, int n1,
                  const float* __restrict__ x2,
                  const int* __restrict__ lab2, int n2) {
    __shared__ Entry         sSorted[ROWS_PB];
    __shared__ const float*  sPtr[ROWS_PB];
    __shared__ int           sCls[ROWS_PB];
    __shared__ int           sPos[ROWS_PB];
    __shared__ int           sCnt[NCEFF];
    __shared__ int           sOff[NCEFF];

    const int tid  = threadIdx.x;
    const int lane = tid & 31;
    const int wid  = tid >> 5;
    const int bid  = blockIdx.x;

    if (tid < NCEFF) sCnt[tid] = 0;
    __syncthreads();

    const int ntot  = n1 + n2;
    const int base  = bid * ROWS_PB;
    const int chunk = min(ROWS_PB, ntot - base);

    // ---- prologue: labels, pointers, counts, ranks ------------------------
    if (tid < chunk) {
        int row = base + tid;
        const float* xp;
        int c;
        if (row < n1) { xp = x1 + (size_t)row * DIM;        c = lab1[row] & (NCLASS - 1); }
        else          { xp = x2 + (size_t)(row - n1) * DIM; c = (lab2[row - n1] & (NCLASS - 1)) + NCLASS; }
        sPtr[tid] = xp;
        sCls[tid] = c;
        sPos[tid] = atomicAdd(&sCnt[c], 1);
    }
    __syncthreads();

    // ---- warp 0: exclusive prefix scan of counts -> bucket offsets --------
    if (wid == 0) {
        int v = sCnt[lane];
        int s = v;
        #pragma unroll
        for (int o = 1; o < 32; o <<= 1) {
            int u = __shfl_up_sync(0xFFFFFFFFu, s, o);
            if (lane >= o) s += u;
        }
        sOff[lane] = s - v;   // exclusive
    }
    __syncthreads();

    // ---- norm pass: warp handles 8 rows, ALL 16 LDG.128 front-batched -----
    {
        const int i0 = wid * ROWS_PW;
        const float4* ps[ROWS_PW];
        #pragma unroll
        for (int j = 0; j < ROWS_PW; j++)
            ps[j] = reinterpret_cast<const float4*>(
                (i0 + j < chunk) ? sPtr[i0 + j] : x1);

        float4 A[ROWS_PW], B[ROWS_PW];
        #pragma unroll
        for (int j = 0; j < ROWS_PW; j++) {
            A[j] = ps[j][lane * 2];
            B[j] = ps[j][lane * 2 + 1];
        }
        float ss[ROWS_PW];
        #pragma unroll
        for (int j = 0; j < ROWS_PW; j++)
            ss[j] = A[j].x * A[j].x + A[j].y * A[j].y + A[j].z * A[j].z + A[j].w * A[j].w
                  + B[j].x * B[j].x + B[j].y * B[j].y + B[j].z * B[j].z + B[j].w * B[j].w;
        #pragma unroll
        for (int o = 16; o > 0; o >>= 1) {
            #pragma unroll
            for (int j = 0; j < ROWS_PW; j++)
                ss[j] += __shfl_xor_sync(0xFFFFFFFFu, ss[j], o);
        }
        if (lane == 0) {
            #pragma unroll
            for (int j = 0; j < ROWS_PW; j++) {
                int i = i0 + j;
                if (i < chunk) {
                    int c   = sCls[i];
                    int idx = sOff[c] + sPos[i];
                    sSorted[idx].ptr = (const float*)ps[j];
                    sSorted[idx].inv = 1.0f / fmaxf(sqrtf(ss[j]), 1e-8f);
                    sSorted[idx].cls = c;
                }
            }
        }
    }
    __syncthreads();

    // ---- phase B: scan sorted runs; dense STG partial tile ------------------
    {
        const int gq = tid >> 6;          // 0..3
        const int q  = tid & (DIMQ - 1);  // 0..63
        #pragma unroll
        for (int ci = 0; ci < 8; ci++) {
            int c = gq * 8 + ci;
            int s = sOff[c];
            int e = s + sCnt[c];
            float4 acc = make_float4(0.f, 0.f, 0.f, 0.f);
            for (int k = s; k < e; k++) {
                Entry en = sSorted[k];                                  // bcast LDS.128
                float4 v = reinterpret_cast<const float4*>(en.ptr)[q];  // L1 hit
                acc.x += v.x * en.inv;
                acc.y += v.y * en.inv;
                acc.z += v.z * en.inv;
                acc.w += v.w * en.inv;
            }
            g_part[bid][c][q] = acc;   // plain STG.128
        }
    }
    if (tid < NCEFF) g_cntp[bid][tid] = sCnt[tid];
}

// ======================= K3: high-MLP reduce + finalize =====================
// grid = 128 blocks: class c = bid>>2, quarter qt = bid&3.
// 256 threads: quad q = tid&63, sub = tid>>6. Thread sums 8 slices.
__global__ void __launch_bounds__(NTHREADS)
ci_reduce_kernel(float* __restrict__ out, int nblk, int n1, int n2) {
    __shared__ float4       sAcc[4][DIMQ];
    __shared__ int          sCntRed[NTHREADS / 32];
    __shared__ unsigned int sIsLast;
    __shared__ double       sRed[NTHREADS / 32];

    const int tid  = threadIdx.x;
    const int lane = tid & 31;
    const int c    = blockIdx.x >> 2;
    const int qt   = blockIdx.x & 3;
    const int q    = tid & (DIMQ - 1);
    const int sub  = tid >> 6;           // 0..3

    // ---- each thread: 8 independent LDG.128 over its slice range ----------
    {
        const int b0 = qt * (nblk >> 2) + sub * (nblk >> 4);   // 8 slices each
        float4 a0 = make_float4(0.f, 0.f, 0.f, 0.f);
        float4 a1 = make_float4(0.f, 0.f, 0.f, 0.f);
        float4 v[8];
        #pragma unroll
        for (int k = 0; k < 8; k++)
            v[k] = g_part[b0 + k][c][q];           // all 8 in flight
        #pragma unroll
        for (int k = 0; k < 8; k += 2) {
            a0.x += v[k].x;   a0.y += v[k].y;   a0.z += v[k].z;   a0.w += v[k].w;
            a1.x += v[k+1].x; a1.y += v[k+1].y; a1.z += v[k+1].z; a1.w += v[k+1].w;
        }
        a0.x += a1.x; a0.y += a1.y; a0.z += a1.z; a0.w += a1.w;
        sAcc[sub][q] = a0;
    }

    // ---- counts: quarter-0 block computes the full class count -------------
    int cnt_part = 0;
    if (qt == 0 && tid < nblk) cnt_part = g_cntp[tid][c];
    __syncthreads();

    if (tid < DIMQ) {
        float4 r0 = sAcc[0][q], r1 = sAcc[1][q], r2 = sAcc[2][q], r3 = sAcc[3][q];
        float4 t;
        t.x = (r0.x + r1.x) + (r2.x + r3.x);
        t.y = (r0.y + r1.y) + (r2.y + r3.y);
        t.z = (r0.z + r1.z) + (r2.z + r3.z);
        t.w = (r0.w + r1.w) + (r2.w + r3.w);
        red_v4(&g_T4[c * DIMQ + q], t);            // 64 v4-REDs per block
    }
    if (qt == 0) {
        #pragma unroll
        for (int o = 16; o > 0; o >>= 1)
            cnt_part += __shfl_xor_sync(0xFFFFFFFFu, cnt_part, o);
        if (lane == 0) sCntRed[tid >> 5] = cnt_part;
        __syncthreads();
        if (tid == 0) {
            int t = 0;
            #pragma unroll
            for (int w = 0; w < NTHREADS / 32; w++) t += sCntRed[w];
            g_cnt[c] = t;
        }
    }

    // ---- election over all K3 blocks ----------------------------------------
    __threadfence();
    __syncthreads();
    if (tid == 0)
        sIsLast = (atomicAdd(&g_done, 1u) == (unsigned)(K3BLKS - 1));
    __syncthreads();
    if (!sIsLast) return;

    // ---- finalize (REDs fenced + visible) ------------------------------------
    const float* gT = (const float*)g_T4;          // [NCEFF*DIM]
    const int d = tid;  // 0..255 == DIM
    double s1 = 0.0, s2 = 0.0, t = 0.0;
    #pragma unroll
    for (int cc = 0; cc < NCLASS; cc++) {
        double av = (double)gT[cc * DIM + d];
        double bv = (double)gT[(cc + NCLASS) * DIM + d];
        s1 += av;
        s2 += bv;
        t  += av * bv;
    }
    double part = s1 * s2 - 2.0 * t;
    #pragma unroll
    for (int o = 16; o > 0; o >>= 1)
        part += __shfl_xor_sync(0xFFFFFFFFu, part, o);
    if (lane == 0) sRed[tid >> 5] = part;
    __syncthreads();
    if (tid == 0) {
        double tot = 0.0;
        #pragma unroll
        for (int w = 0; w < NTHREADS / 32; w++) tot += sRed[w];
        double cc = 0.0;
        #pragma unroll
        for (int k = 0; k < NCLASS; k++)
            cc += (double)g_cnt[k] * (double)g_cnt[k + NCLASS];
        out[0] = (float)((tot + cc) / ((double)n1 * (double)n2));
    }
    __syncthreads();   // all threads done reading g_T4

    // ---- re-zero RED-accumulated state for next graph replay ----------------
    {
        float4 z = make_float4(0.f, 0.f, 0.f, 0.f);
        #pragma unroll
        for (int i = 0; i < (NCEFF * DIMQ) / NTHREADS; i++)
            g_T4[i * NTHREADS + tid] = z;
    }
    if (tid == 0) g_done = 0u;
}

extern "C" void kernel_launch(void* const* d_in, const int* in_sizes, int n_in,
                              void* d_out, int out_size) {
    const float* mmd1 = (const float*)d_in[0];
    const float* mmd2 = (const float*)d_in[1];
    const int*   lab1 = (const int*)d_in[2];
    const int*   lab2 = (const int*)d_in[3];

    int n1 = in_sizes[0] / DIM;
    int n2 = in_sizes[1] / DIM;
    int ntot = n1 + n2;
    int nblk = (ntot + ROWS_PB - 1) / ROWS_PB;
    if (nblk > MAXBLK) nblk = MAXBLK;   // fixed shapes: 128 exactly

    ci_partial_kernel<<<nblk, NTHREADS>>>(mmd1, lab1, n1, mmd2, lab2, n2);
    ci_reduce_kernel<<<K3BLKS, NTHREADS>>>((float*)d_out, nblk, n1, n2);
}

// round 12
// speedup vs baseline: 1.5000x; 1.0960x over previous
#include <cuda_runtime.h>
#include <cuda_bf16.h>
#include <math.h>

// ---------------------------------------------------------------------------
// mean over all (i,j) of: same(i,j) ? max(1-cos,0) : cos, with cos = pairwise
// cosine of row-normalized inputs.
//
// Algebraic collapse (clamp provably inactive; rel_err==0.0 confirmed):
//   sum = S1.S2 + sum_c [ cnt1_c*cnt2_c - 2 * T1_c . T2_c ]
// T_c = class-sum of normalized rows.  O(N*D).
//
// R11: R10's K3 got regs=40 -> ptxas serialized the 8 loads (MLP~2).
// New K3: 512 blocks, each thread loads exactly TWO float4 slices (one
// load wave, no register pressure), smem combine, 64 v4-REDs/block,
// election + finalize. K2 unchanged (proven 2.7us).
// ---------------------------------------------------------------------------

#define NCLASS   16
#define NCEFF    32           // 16 classes x 2 tensors
#define DIM      256
#define DIMQ     (DIM / 4)    // 64 dim-quads
#define ROWS_PB  64
#define MAXBLK   128          // (4096+4096)/64
#define NTHREADS 256
#define ROWS_PW  8            // rows per warp in K2 norm pass
#define K3BLKS   (NCEFF * 16) // 512

struct __align__(16) Entry {
    const float* ptr;
    float        inv;
    int          cls;
};

__device__ float4       g_part[MAXBLK][NCEFF][DIMQ];  // 4 MB, dense overwrite
__device__ int          g_cntp[MAXBLK][NCEFF];        // dense overwrite
__device__ float4       g_T4[NCEFF * DIMQ];           // RED-accumulated; last K3 block zeroes
__device__ int          g_cnt[NCEFF];                 // STG overwrite
__device__ unsigned int g_done;

__device__ __forceinline__ void red_v4(float4* p, float4 v) {
    asm volatile("red.global.add.v4.f32 [%0], {%1, %2, %3, %4};"
                 :: "l"(p), "f"(v.x), "f"(v.y), "f"(v.z), "f"(v.w)
                 : "memory");
}

// ======================= K2: per-block partial tiles ========================
__global__ void __launch_bounds__(NTHREADS, 1)
ci_partial_kernel(const float* __restrict__ x1,
                  const int* __restrict__ lab1, int n1,
                  const float* __restrict__ x2,
                  const int* __restrict__ lab2, int n2) {
    __shared__ Entry         sSorted[ROWS_PB];
    __shared__ const float*  sPtr[ROWS_PB];
    __shared__ int           sCls[ROWS_PB];
    __shared__ int           sPos[ROWS_PB];
    __shared__ int           sCnt[NCEFF];
    __shared__ int           sOff[NCEFF];

    const int tid  = threadIdx.x;
    const int lane = tid & 31;
    const int wid  = tid >> 5;
    const int bid  = blockIdx.x;

    if (tid < NCEFF) sCnt[tid] = 0;
    __syncthreads();

    const int ntot  = n1 + n2;
    const int base  = bid * ROWS_PB;
    const int chunk = min(ROWS_PB, ntot - base);

    // ---- prologue: labels, pointers, counts, ranks ------------------------
    if (tid < chunk) {
        int row = base + tid;
        const float* xp;
        int c;
        if (row < n1) { xp = x1 + (size_t)row * DIM;        c = lab1[row] & (NCLASS - 1); }
        else          { xp = x2 + (size_t)(row - n1) * DIM; c = (lab2[row - n1] & (NCLASS - 1)) + NCLASS; }
        sPtr[tid] = xp;
        sCls[tid] = c;
        sPos[tid] = atomicAdd(&sCnt[c], 1);
    }
    __syncthreads();

    // ---- warp 0: exclusive prefix scan of counts -> bucket offsets --------
    if (wid == 0) {
        int v = sCnt[lane];
        int s = v;
        #pragma unroll
        for (int o = 1; o < 32; o <<= 1) {
            int u = __shfl_up_sync(0xFFFFFFFFu, s, o);
            if (lane >= o) s += u;
        }
        sOff[lane] = s - v;   // exclusive
    }
    __syncthreads();

    // ---- norm pass: warp handles 8 rows, ALL 16 LDG.128 front-batched -----
    {
        const int i0 = wid * ROWS_PW;
        const float4* ps[ROWS_PW];
        #pragma unroll
        for (int j = 0; j < ROWS_PW; j++)
            ps[j] = reinterpret_cast<const float4*>(
                (i0 + j < chunk) ? sPtr[i0 + j] : x1);

        float4 A[ROWS_PW], B[ROWS_PW];
        #pragma unroll
        for (int j = 0; j < ROWS_PW; j++) {
            A[j] = ps[j][lane * 2];
            B[j] = ps[j][lane * 2 + 1];
        }
        float ss[ROWS_PW];
        #pragma unroll
        for (int j = 0; j < ROWS_PW; j++)
            ss[j] = A[j].x * A[j].x + A[j].y * A[j].y + A[j].z * A[j].z + A[j].w * A[j].w
                  + B[j].x * B[j].x + B[j].y * B[j].y + B[j].z * B[j].z + B[j].w * B[j].w;
        #pragma unroll
        for (int o = 16; o > 0; o >>= 1) {
            #pragma unroll
            for (int j = 0; j < ROWS_PW; j++)
                ss[j] += __shfl_xor_sync(0xFFFFFFFFu, ss[j], o);
        }
        if (lane == 0) {
            #pragma unroll
            for (int j = 0; j < ROWS_PW; j++) {
                int i = i0 + j;
                if (i < chunk) {
                    int c   = sCls[i];
                    int idx = sOff[c] + sPos[i];
                    sSorted[idx].ptr = (const float*)ps[j];
                    sSorted[idx].inv = 1.0f / fmaxf(sqrtf(ss[j]), 1e-8f);
                    sSorted[idx].cls = c;
                }
            }
        }
    }
    __syncthreads();

    // ---- phase B: scan sorted runs; dense STG partial tile ------------------
    {
        const int gq = tid >> 6;          // 0..3
        const int q  = tid & (DIMQ - 1);  // 0..63
        #pragma unroll
        for (int ci = 0; ci < 8; ci++) {
            int c = gq * 8 + ci;
            int s = sOff[c];
            int e = s + sCnt[c];
            float4 acc = make_float4(0.f, 0.f, 0.f, 0.f);
            for (int k = s; k < e; k++) {
                Entry en = sSorted[k];                                  // bcast LDS.128
                float4 v = reinterpret_cast<const float4*>(en.ptr)[q];  // L1 hit
                acc.x += v.x * en.inv;
                acc.y += v.y * en.inv;
                acc.z += v.z * en.inv;
                acc.w += v.w * en.inv;
            }
            g_part[bid][c][q] = acc;   // plain STG.128
        }
    }
    if (tid < NCEFF) g_cntp[bid][tid] = sCnt[tid];
}

// ======================= K3: one-load-wave reduce + finalize ================
// grid = 512: class c = bid>>4, sixteenth st = bid&15 (8 slices each).
// 256 threads: quad q = tid&63, sub = tid>>6 -> thread loads 2 slices.
__global__ void __launch_bounds__(NTHREADS, 1)
ci_reduce_kernel(float* __restrict__ out, int nblk, int n1, int n2) {
    __shared__ float4       sAcc[4][DIMQ];
    __shared__ int          sCntRed[NTHREADS / 32];
    __shared__ unsigned int sIsLast;
    __shared__ double       sRed[NTHREADS / 32];

    const int tid  = threadIdx.x;
    const int lane = tid & 31;
    const int c    = blockIdx.x >> 4;
    const int st   = blockIdx.x & 15;
    const int q    = tid & (DIMQ - 1);
    const int sub  = tid >> 6;           // 0..3

    // ---- exactly 2 independent LDG.128 per thread (single load wave) -------
    {
        const int b0 = st * 8 + sub * 2;
        float4 v0 = g_part[b0][c][q];
        float4 v1 = g_part[b0 + 1][c][q];
        v0.x += v1.x; v0.y += v1.y; v0.z += v1.z; v0.w += v1.w;
        sAcc[sub][q] = v0;
    }

    // ---- counts staged in parallel with the loads ---------------------------
    int cnt_part = 0;
    if (st == 0 && tid < nblk) cnt_part = g_cntp[tid][c];
    __syncthreads();

    if (tid < DIMQ) {
        float4 r0 = sAcc[0][q], r1 = sAcc[1][q], r2 = sAcc[2][q], r3 = sAcc[3][q];
        float4 t;
        t.x = (r0.x + r1.x) + (r2.x + r3.x);
        t.y = (r0.y + r1.y) + (r2.y + r3.y);
        t.z = (r0.z + r1.z) + (r2.z + r3.z);
        t.w = (r0.w + r1.w) + (r2.w + r3.w);
        red_v4(&g_T4[c * DIMQ + q], t);            // 64 v4-REDs per block
    }
    if (st == 0) {
        #pragma unroll
        for (int o = 16; o > 0; o >>= 1)
            cnt_part += __shfl_xor_sync(0xFFFFFFFFu, cnt_part, o);
        if (lane == 0) sCntRed[tid >> 5] = cnt_part;
        __syncthreads();
        if (tid == 0) {
            int t = 0;
            #pragma unroll
            for (int w = 0; w < NTHREADS / 32; w++) t += sCntRed[w];
            g_cnt[c] = t;
        }
    }

    // ---- election over all K3 blocks ----------------------------------------
    __threadfence();
    __syncthreads();
    if (tid == 0)
        sIsLast = (atomicAdd(&g_done, 1u) == (unsigned)(K3BLKS - 1));
    __syncthreads();
    if (!sIsLast) return;

    // ---- finalize (REDs fenced + visible) ------------------------------------
    const float* gT = (const float*)g_T4;          // [NCEFF*DIM]
    const int d = tid;  // 0..255 == DIM
    double s1 = 0.0, s2 = 0.0, t = 0.0;
    #pragma unroll
    for (int cc = 0; cc < NCLASS; cc++) {
        double av = (double)gT[cc * DIM + d];
        double bv = (double)gT[(cc + NCLASS) * DIM + d];
        s1 += av;
        s2 += bv;
        t  += av * bv;
    }
    double part = s1 * s2 - 2.0 * t;
    #pragma unroll
    for (int o = 16; o > 0; o >>= 1)
        part += __shfl_xor_sync(0xFFFFFFFFu, part, o);
    if (lane == 0) sRed[tid >> 5] = part;
    __syncthreads();
    if (tid == 0) {
        double tot = 0.0;
        #pragma unroll
        for (int w = 0; w < NTHREADS / 32; w++) tot += sRed[w];
        double cc = 0.0;
        #pragma unroll
        for (int k = 0; k < NCLASS; k++)
            cc += (double)g_cnt[k] * (double)g_cnt[k + NCLASS];
        out[0] = (float)((tot + cc) / ((double)n1 * (double)n2));
    }
    __syncthreads();   // all threads done reading g_T4

    // ---- re-zero RED-accumulated state for next graph replay ----------------
    {
        float4 z = make_float4(0.f, 0.f, 0.f, 0.f);
        #pragma unroll
        for (int i = 0; i < (NCEFF * DIMQ) / NTHREADS; i++)
            g_T4[i * NTHREADS + tid] = z;
    }
    if (tid == 0) g_done = 0u;
}

extern "C" void kernel_launch(void* const* d_in, const int* in_sizes, int n_in,
                              void* d_out, int out_size) {
    const float* mmd1 = (const float*)d_in[0];
    const float* mmd2 = (const float*)d_in[1];
    const int*   lab1 = (const int*)d_in[2];
    const int*   lab2 = (const int*)d_in[3];

    int n1 = in_sizes[0] / DIM;
    int n2 = in_sizes[1] / DIM;
    int ntot = n1 + n2;
    int nblk = (ntot + ROWS_PB - 1) / ROWS_PB;
    if (nblk > MAXBLK) nblk = MAXBLK;   // fixed shapes: 128 exactly

    ci_partial_kernel<<<nblk, NTHREADS>>>(mmd1, lab1, n1, mmd2, lab2, n2);
    ci_reduce_kernel<<<K3BLKS, NTHREADS>>>((float*)d_out, nblk, n1, n2);
}